// round 16
// baseline (speedup 1.0000x reference)
#include <cuda_runtime.h>
#include <math.h>
#include <string.h>

// CausalSTFT via Hann window + even/odd pack + 512-pt radix-8^3 register FFT
// + Hermitian-pair recombination. Packed f32x2 arithmetic.
// R15 = R14 math verbatim, reshaped FPB 8->4 / NT 512->256:
//   6 CTAs/SM (was 3) at the same 48 warps/SM -> barrier groups halve (8 warps)
//   and independent-CTA overlap doubles, attacking the exposed-latency gap
//   (issue 48.7%, L1 66.2%, nothing saturated).
// Plus: unguarded 7-iteration staging fast path for blockIdx.x > 0.

#define HOPK 256
#define FPB  4            // frames per block
#define NT   256          // threads per block
#define TFR  2048         // frames per batch row
#define KB   513          // output bins
#define TILE_IN 1792      // samples spanned by 4 overlapping frames
#define ZS   578          // per-frame float2 stride in s_z

// ---------- packed f32x2 helpers ----------
__device__ __forceinline__ unsigned long long F2U(float2 a) {
    unsigned long long u; memcpy(&u, &a, 8); return u;
}
__device__ __forceinline__ float2 U2F(unsigned long long u) {
    float2 a; memcpy(&a, &u, 8); return a;
}
#define PK_NEG1 0xBF800000BF800000ULL   // (-1.f, -1.f)
#define PK_PM1  0xBF8000003F800000ULL   // ( 1.f, -1.f)  (lo=x, hi=y)
#define PK_CC   0x3F3504F33F3504F3ULL   // (C, C), C = cos(pi/4)

__device__ __forceinline__ float2 padd(float2 a, float2 b) {
    unsigned long long r;
    asm("add.rn.f32x2 %0, %1, %2;" : "=l"(r) : "l"(F2U(a)), "l"(F2U(b)));
    return U2F(r);
}
__device__ __forceinline__ float2 pfmac(float2 a, unsigned long long c, float2 b) {
    unsigned long long r;
    asm("fma.rn.f32x2 %0, %1, %2, %3;" : "=l"(r) : "l"(F2U(a)), "l"(c), "l"(F2U(b)));
    return U2F(r);
}
__device__ __forceinline__ float2 psub(float2 a, float2 b) {   // a - b
    return pfmac(b, PK_NEG1, a);
}
__device__ __forceinline__ float2 pscale(float2 a, unsigned long long c) {
    unsigned long long r;
    asm("mul.rn.f32x2 %0, %1, %2;" : "=l"(r) : "l"(F2U(a)), "l"(c));
    return U2F(r);
}
__device__ __forceinline__ float2 pmul(float2 a, float2 b) {
    unsigned long long r;
    asm("mul.rn.f32x2 %0, %1, %2;" : "=l"(r) : "l"(F2U(a)), "l"(F2U(b)));
    return U2F(r);
}
__device__ __forceinline__ float2 mul_mi(float2 a) { return make_float2(a.y, -a.x); } // * -i

__device__ __forceinline__ float2 cmul(float2 a, float2 b) {
    return make_float2(fmaf(a.x, b.x, -a.y * b.y), fmaf(a.x, b.y, a.y * b.x));
}

// v[r] <- sum_j v[j] * W8^{j r},  W8 = e^{-i pi/4}.  In-place DIF radix-8.
__device__ __forceinline__ void dif8(float2* v) {
    float2 u0 = padd(v[0], v[4]), u4 = psub(v[0], v[4]);
    float2 u1 = padd(v[1], v[5]), u5 = psub(v[1], v[5]);
    float2 u2 = padd(v[2], v[6]), u6 = psub(v[2], v[6]);
    float2 u3 = padd(v[3], v[7]), u7 = psub(v[3], v[7]);
    u5 = pscale(padd(u5, mul_mi(u5)), PK_CC);         // * W8^1
    u6 = mul_mi(u6);                                  // * W8^2 = -i
    u7 = pscale(mul_mi(padd(u7, mul_mi(u7))), PK_CC); // * W8^3
    float2 t0 = padd(u0, u2), t2 = psub(u0, u2);
    float2 t1 = padd(u1, u3), t3 = mul_mi(psub(u1, u3));
    v[0] = padd(t0, t1); v[4] = psub(t0, t1);
    v[2] = padd(t2, t3); v[6] = psub(t2, t3);
    t0 = padd(u4, u6); t2 = psub(u4, u6);
    t1 = padd(u5, u7); t3 = mul_mi(psub(u5, u7));
    v[1] = padd(t0, t1); v[5] = psub(t0, t1);
    v[3] = padd(t2, t3); v[7] = psub(t2, t3);
}

// v[r] *= w^r. Powers via packed Chebyshev recurrence:
//   w^{r+1} = 2*Re(w) * w^r - w^{r-1}   (componentwise on (cos,sin))
__device__ __forceinline__ void twiddle_chain(float2* v, float2 w) {
    unsigned long long c2 = F2U(make_float2(2.0f * w.x, 2.0f * w.x));
    float2 wm = make_float2(1.0f, 0.0f);
    float2 wp = w;
    v[1] = cmul(v[1], wp);
    #pragma unroll
    for (int r = 2; r < 8; ++r) {
        float2 wn = psub(pscale(wp, c2), wm);
        wm = wp; wp = wn;
        v[r] = cmul(v[r], wn);
    }
}

__device__ __forceinline__ float sqrt_approx(float x) {
    float r;
    asm("sqrt.approx.f32 %0, %1;" : "=f"(r) : "f"(x));
    return r;
}

__global__ __launch_bounds__(NT, 6) void causal_stft_kernel(
    const float* __restrict__ x,
    const float* __restrict__ weight,     // row 0 (first 1024 floats) = Hann window
    float* __restrict__ out)
{
    __shared__ float2 s_z[FPB * ZS];      // 18,496 B  (FFT workspace)
    __shared__ float2 s_in[TILE_IN / 2];  //  7,168 B  (input tile; later W1024^k table)
    __shared__ float2 s_t512[64];         //    512 B  (W512^j)
    __shared__ float2 s_t64[8];           //     64 B  (W64^p)

    const int tid = threadIdx.x;
    const int b   = blockIdx.y;
    const int t0  = blockIdx.x * FPB;
    const int f   = tid >> 6;             // frame 0..3
    const int l   = tid & 63;             // lane within frame
    const float* xb = x + (size_t)b * (size_t)(HOPK * TFR);
    const int g0 = t0 * HOPK - 1023;

    // ---- base twiddle tables + input tile (one barrier covers all) ----
    if (tid < 64) {
        float s, c;
        sincospif(-(float)tid * (1.0f / 256.0f), &s, &c);   // W512^j
        s_t512[tid] = make_float2(c, s);
    } else if (tid < 72) {
        float s, c;
        sincospif(-(float)(tid - 64) * (1.0f / 32.0f), &s, &c); // W64^p
        s_t64[tid - 64] = make_float2(c, s);
    }
    {
        float* s_inf = (float*)s_in;
        if (blockIdx.x == 0) {                          // only block 0 sees g < 0
            for (int u = tid; u < TILE_IN; u += NT) {
                int g = g0 + u;
                s_inf[u] = (g >= 0) ? __ldg(xb + g) : 0.0f;
            }
        } else {
            const float* src = xb + g0;
            #pragma unroll
            for (int i = 0; i < TILE_IN / NT; ++i)      // exactly 7 iterations
                s_inf[tid + i * NT] = __ldg(src + tid + i * NT);
        }
    }
    __syncthreads();

    float2 v[8];
    float2* zf = s_z + f * ZS;

    // ---- stage A: window + pack + radix-8 over j (stride 64) + W512^{l r} ----
    {
        const float2* w2 = (const float2*)weight;
        #pragma unroll
        for (int j = 0; j < 8; ++j) {
            float2 xin = s_in[f * 128 + l + 64 * j];    // (x[2m], x[2m+1]), m=l+64j
            float2 wv  = __ldg(&w2[l + 64 * j]);
            v[j] = pmul(xin, wv);
        }
        dif8(v);                                        // v[r] = A_l[r]
        twiddle_chain(v, s_t512[l]);                    // * W512^{l r}
        #pragma unroll
        for (int r = 0; r < 8; ++r)                     // consecutive -> CF
            zf[72 * r + l] = v[r];
    }
    __syncthreads();

    // ---- fill W1024^k table (k=0..256) into dead s_in space ----
    for (int j = tid; j < 257; j += NT) {
        float s, c;
        sincospif(-(float)j * (1.0f / 512.0f), &s, &c); // e^{-2pi i j/1024}
        s_in[j] = make_float2(c, s);
    }

    // ---- stage B: radix-8 over q (stride 8) + W64^{p m1} ----
    // Row r is touched only by lanes 8r..8r+7 (one warp) -> warp-local guard.
    {
        const int r = l >> 3, p = l & 7;
        float2* zr = zf + 72 * r;
        #pragma unroll
        for (int q = 0; q < 8; ++q)                     // CF (mod-16 transversal)
            v[q] = zr[p + 8 * q];
        dif8(v);                                        // v[m1] = C_{r,p}[m1]
        twiddle_chain(v, s_t64[p]);                     // * W64^{p m1}
        __syncwarp();                                   // row-local: same warp only
        #pragma unroll
        for (int m1 = 0; m1 < 8; ++m1)                  // CF
            zr[9 * m1 + p] = v[m1];
    }
    __syncthreads();

    // ---- stage C: final radix-8 over p, store natural order at phi(k)=k+(k>>3) ----
    {
        const int r = l >> 3, m1 = l & 7;
        float2* zr = zf + 72 * r + 9 * m1;
        #pragma unroll
        for (int p = 0; p < 8; ++p)                     // CF
            v[p] = zr[p];
        dif8(v);                                        // v[m2] = Z[r + 8 m1 + 64 m2]
        __syncthreads();                                // C writes cross warps' reads
        const int base2 = r + 9 * m1;                   // phi(r+8m1+64m2) = r+9m1+72m2
        #pragma unroll
        for (int m2 = 0; m2 < 8; ++m2)
            zf[base2 + 72 * m2] = v[m2];
    }
    __syncthreads();                                    // epilogue reads cross-frame

    // ---- Hermitian-pair recombination + magnitude ----
    // X[k]     = E + W1024^k O        (read at phi(k))
    // X[512-k] = conj(E - W1024^k O)  -> same loads, second output
    // Values here are 2E, 2O; 0.5 folded into the final magnitude.
    {
        const int ff = tid & 3;                         // frame 0..3
        const float2* zo = s_z + ff * ZS;
        float* ob = out + ((size_t)b * KB) * TFR + (t0 + ff);
        int k = tid >> 2;                               // 0..63
        #pragma unroll
        for (int i = 0; i < 5; ++i, k += 64) {
            if (k <= 256) {
                int km = (512 - k) & 511;
                float2 Zk = zo[k  + (k  >> 3)];
                float2 Zm = zo[km + (km >> 3)];
                float2 E = pfmac(Zm, PK_PM1, Zk);       // 2E
                float2 O = padd(mul_mi(Zk), make_float2(Zm.y, Zm.x)); // 2O
                float2 tw = s_in[k];
                float tr = fmaf(tw.x, O.x, -tw.y * O.y);  // 2*(tw*O)
                float ti = fmaf(tw.x, O.y,  tw.y * O.x);
                float2 T  = make_float2(tr, ti);
                float2 X1 = padd(E, T);                 // 2*X[k]
                float2 X2 = psub(E, T);                 // 2*conj(X[512-k])
                float p1 = fmaxf(fmaf(X1.x, X1.x, X1.y * X1.y), 4e-12f);
                float p2 = fmaxf(fmaf(X2.x, X2.x, X2.y * X2.y), 4e-12f);
                ob[(size_t)k * TFR]         = 0.5f * sqrt_approx(p1);
                ob[(size_t)(512 - k) * TFR] = 0.5f * sqrt_approx(p2);
            }
        }
    }
}

extern "C" void kernel_launch(void* const* d_in, const int* in_sizes, int n_in,
                              void* d_out, int out_size)
{
    const float* x = (const float*)d_in[0];
    const float* w = (const float*)d_in[1];
    int xs = in_sizes[0];
    if (n_in >= 2 && in_sizes[0] < in_sizes[1]) {   // x is the larger tensor
        const float* t = x; x = w; w = t;
        xs = in_sizes[1];
    }
    int B = xs / (HOPK * TFR);                      // 16
    dim3 grid(TFR / FPB, B);
    causal_stft_kernel<<<grid, NT>>>(x, w, (float*)d_out);
}

// round 17
// speedup vs baseline: 1.0618x; 1.0618x over previous
#include <cuda_runtime.h>
#include <math.h>
#include <string.h>

// CausalSTFT via Hann window + even/odd pack + 512-pt radix-8^3 register FFT
// + Hermitian-pair recombination. Packed f32x2 arithmetic.
// R16 = R14 byte-for-byte (best kernel, 64.8us at NT=512/FPB=8, L1=66%,
// issue=49%, occ=69% @ regs=40/3 CTAs) with ONE change:
//   __launch_bounds__(512, 4)  -> regs capped at 32, 4 CTAs/SM, 64 warps/SM.
// R15 (NT=256) proved L1 has headroom to ~86% if concurrency rises; this buys
// +33% resident warps with zero added per-block overhead, at the cost of a
// few register spills.

#define HOPK 256
#define FPB  8            // frames per block
#define NT   512          // threads per block
#define TFR  2048         // frames per batch row
#define KB   513          // output bins
#define TILE_IN 2816      // samples spanned by 8 overlapping frames
#define ZS   578          // per-frame float2 stride in s_z

// ---------- packed f32x2 helpers ----------
__device__ __forceinline__ unsigned long long F2U(float2 a) {
    unsigned long long u; memcpy(&u, &a, 8); return u;
}
__device__ __forceinline__ float2 U2F(unsigned long long u) {
    float2 a; memcpy(&a, &u, 8); return a;
}
#define PK_NEG1 0xBF800000BF800000ULL   // (-1.f, -1.f)
#define PK_PM1  0xBF8000003F800000ULL   // ( 1.f, -1.f)  (lo=x, hi=y)
#define PK_CC   0x3F3504F33F3504F3ULL   // (C, C), C = cos(pi/4)

__device__ __forceinline__ float2 padd(float2 a, float2 b) {
    unsigned long long r;
    asm("add.rn.f32x2 %0, %1, %2;" : "=l"(r) : "l"(F2U(a)), "l"(F2U(b)));
    return U2F(r);
}
__device__ __forceinline__ float2 pfmac(float2 a, unsigned long long c, float2 b) {
    unsigned long long r;
    asm("fma.rn.f32x2 %0, %1, %2, %3;" : "=l"(r) : "l"(F2U(a)), "l"(c), "l"(F2U(b)));
    return U2F(r);
}
__device__ __forceinline__ float2 psub(float2 a, float2 b) {   // a - b
    return pfmac(b, PK_NEG1, a);
}
__device__ __forceinline__ float2 pscale(float2 a, unsigned long long c) {
    unsigned long long r;
    asm("mul.rn.f32x2 %0, %1, %2;" : "=l"(r) : "l"(F2U(a)), "l"(c));
    return U2F(r);
}
__device__ __forceinline__ float2 pmul(float2 a, float2 b) {
    unsigned long long r;
    asm("mul.rn.f32x2 %0, %1, %2;" : "=l"(r) : "l"(F2U(a)), "l"(F2U(b)));
    return U2F(r);
}
__device__ __forceinline__ float2 mul_mi(float2 a) { return make_float2(a.y, -a.x); } // * -i

__device__ __forceinline__ float2 cmul(float2 a, float2 b) {
    return make_float2(fmaf(a.x, b.x, -a.y * b.y), fmaf(a.x, b.y, a.y * b.x));
}

// v[r] <- sum_j v[j] * W8^{j r},  W8 = e^{-i pi/4}.  In-place DIF radix-8.
__device__ __forceinline__ void dif8(float2* v) {
    float2 u0 = padd(v[0], v[4]), u4 = psub(v[0], v[4]);
    float2 u1 = padd(v[1], v[5]), u5 = psub(v[1], v[5]);
    float2 u2 = padd(v[2], v[6]), u6 = psub(v[2], v[6]);
    float2 u3 = padd(v[3], v[7]), u7 = psub(v[3], v[7]);
    u5 = pscale(padd(u5, mul_mi(u5)), PK_CC);         // * W8^1
    u6 = mul_mi(u6);                                  // * W8^2 = -i
    u7 = pscale(mul_mi(padd(u7, mul_mi(u7))), PK_CC); // * W8^3
    float2 t0 = padd(u0, u2), t2 = psub(u0, u2);
    float2 t1 = padd(u1, u3), t3 = mul_mi(psub(u1, u3));
    v[0] = padd(t0, t1); v[4] = psub(t0, t1);
    v[2] = padd(t2, t3); v[6] = psub(t2, t3);
    t0 = padd(u4, u6); t2 = psub(u4, u6);
    t1 = padd(u5, u7); t3 = mul_mi(psub(u5, u7));
    v[1] = padd(t0, t1); v[5] = psub(t0, t1);
    v[3] = padd(t2, t3); v[7] = psub(t2, t3);
}

// v[r] *= w^r. Powers via packed Chebyshev recurrence:
//   w^{r+1} = 2*Re(w) * w^r - w^{r-1}   (componentwise on (cos,sin))
__device__ __forceinline__ void twiddle_chain(float2* v, float2 w) {
    unsigned long long c2 = F2U(make_float2(2.0f * w.x, 2.0f * w.x));
    float2 wm = make_float2(1.0f, 0.0f);
    float2 wp = w;
    v[1] = cmul(v[1], wp);
    #pragma unroll
    for (int r = 2; r < 8; ++r) {
        float2 wn = psub(pscale(wp, c2), wm);
        wm = wp; wp = wn;
        v[r] = cmul(v[r], wn);
    }
}

__device__ __forceinline__ float sqrt_approx(float x) {
    float r;
    asm("sqrt.approx.f32 %0, %1;" : "=f"(r) : "f"(x));
    return r;
}

__global__ __launch_bounds__(NT, 4) void causal_stft_kernel(
    const float* __restrict__ x,
    const float* __restrict__ weight,     // row 0 (first 1024 floats) = Hann window
    float* __restrict__ out)
{
    __shared__ float2 s_z[FPB * ZS];      // 36,992 B  (FFT workspace)
    __shared__ float2 s_in[TILE_IN / 2];  // 11,264 B  (input tile; later W1024^k table)
    __shared__ float2 s_t512[64];         //    512 B  (W512^j)
    __shared__ float2 s_t64[8];           //     64 B  (W64^p)

    const int tid = threadIdx.x;
    const int b   = blockIdx.y;
    const int t0  = blockIdx.x * FPB;
    const int f   = tid >> 6;             // frame 0..7
    const int l   = tid & 63;             // lane within frame
    const float* xb = x + (size_t)b * (size_t)(HOPK * TFR);
    const int g0 = t0 * HOPK - 1023;

    // ---- base twiddle tables + input tile (one barrier covers all) ----
    if (tid < 64) {
        float s, c;
        sincospif(-(float)tid * (1.0f / 256.0f), &s, &c);   // W512^j
        s_t512[tid] = make_float2(c, s);
    } else if (tid < 72) {
        float s, c;
        sincospif(-(float)(tid - 64) * (1.0f / 32.0f), &s, &c); // W64^p
        s_t64[tid - 64] = make_float2(c, s);
    }
    {
        float* s_inf = (float*)s_in;
        for (int u = tid; u < TILE_IN; u += NT) {
            int g = g0 + u;
            s_inf[u] = (g >= 0) ? __ldg(xb + g) : 0.0f;     // left edge zero-pad
        }
    }
    __syncthreads();

    float2 v[8];
    float2* zf = s_z + f * ZS;

    // ---- stage A: window + pack + radix-8 over j (stride 64) + W512^{l r} ----
    {
        const float2* w2 = (const float2*)weight;
        #pragma unroll
        for (int j = 0; j < 8; ++j) {
            float2 xin = s_in[f * 128 + l + 64 * j];    // (x[2m], x[2m+1]), m=l+64j
            float2 wv  = __ldg(&w2[l + 64 * j]);
            v[j] = pmul(xin, wv);
        }
        dif8(v);                                        // v[r] = A_l[r]
        twiddle_chain(v, s_t512[l]);                    // * W512^{l r}
        #pragma unroll
        for (int r = 0; r < 8; ++r)                     // consecutive -> CF
            zf[72 * r + l] = v[r];
    }
    __syncthreads();

    // ---- fill W1024^k table (k=0..256) into dead s_in space ----
    for (int j = tid; j < 257; j += NT) {
        float s, c;
        sincospif(-(float)j * (1.0f / 512.0f), &s, &c); // e^{-2pi i j/1024}
        s_in[j] = make_float2(c, s);
    }

    // ---- stage B: radix-8 over q (stride 8) + W64^{p m1} ----
    // Row r is touched only by lanes 8r..8r+7 (one warp) -> warp-local guard.
    {
        const int r = l >> 3, p = l & 7;
        float2* zr = zf + 72 * r;
        #pragma unroll
        for (int q = 0; q < 8; ++q)                     // CF (mod-16 transversal)
            v[q] = zr[p + 8 * q];
        dif8(v);                                        // v[m1] = C_{r,p}[m1]
        twiddle_chain(v, s_t64[p]);                     // * W64^{p m1}
        __syncwarp();                                   // row-local: same warp only
        #pragma unroll
        for (int m1 = 0; m1 < 8; ++m1)                  // CF
            zr[9 * m1 + p] = v[m1];
    }
    __syncthreads();

    // ---- stage C: final radix-8 over p, store natural order at phi(k)=k+(k>>3) ----
    {
        const int r = l >> 3, m1 = l & 7;
        float2* zr = zf + 72 * r + 9 * m1;
        #pragma unroll
        for (int p = 0; p < 8; ++p)                     // CF
            v[p] = zr[p];
        dif8(v);                                        // v[m2] = Z[r + 8 m1 + 64 m2]
        __syncthreads();                                // C writes cross warps' reads
        const int base2 = r + 9 * m1;                   // phi(r+8m1+64m2) = r+9m1+72m2
        #pragma unroll
        for (int m2 = 0; m2 < 8; ++m2)
            zf[base2 + 72 * m2] = v[m2];
    }
    __syncthreads();                                    // epilogue reads cross-frame

    // ---- Hermitian-pair recombination + magnitude ----
    // X[k]     = E + W1024^k O        (read at phi(k))
    // X[512-k] = conj(E - W1024^k O)  -> same loads, second output
    // Values here are 2E, 2O; 0.5 folded into the final magnitude.
    {
        const int ff = tid & 7;
        const float2* zo = s_z + ff * ZS;
        float* ob = out + ((size_t)b * KB) * TFR + (t0 + ff);
        int k = tid >> 3;                               // 0..63
        #pragma unroll
        for (int i = 0; i < 5; ++i, k += 64) {
            if (k <= 256) {
                int km = (512 - k) & 511;
                float2 Zk = zo[k  + (k  >> 3)];
                float2 Zm = zo[km + (km >> 3)];
                float2 E = pfmac(Zm, PK_PM1, Zk);       // 2E
                float2 O = padd(mul_mi(Zk), make_float2(Zm.y, Zm.x)); // 2O
                float2 tw = s_in[k];
                float tr = fmaf(tw.x, O.x, -tw.y * O.y);  // 2*(tw*O)
                float ti = fmaf(tw.x, O.y,  tw.y * O.x);
                float2 T  = make_float2(tr, ti);
                float2 X1 = padd(E, T);                 // 2*X[k]
                float2 X2 = psub(E, T);                 // 2*conj(X[512-k])
                float p1 = fmaxf(fmaf(X1.x, X1.x, X1.y * X1.y), 4e-12f);
                float p2 = fmaxf(fmaf(X2.x, X2.x, X2.y * X2.y), 4e-12f);
                ob[(size_t)k * TFR]         = 0.5f * sqrt_approx(p1);
                ob[(size_t)(512 - k) * TFR] = 0.5f * sqrt_approx(p2);
            }
        }
    }
}

extern "C" void kernel_launch(void* const* d_in, const int* in_sizes, int n_in,
                              void* d_out, int out_size)
{
    const float* x = (const float*)d_in[0];
    const float* w = (const float*)d_in[1];
    int xs = in_sizes[0];
    if (n_in >= 2 && in_sizes[0] < in_sizes[1]) {   // x is the larger tensor
        const float* t = x; x = w; w = t;
        xs = in_sizes[1];
    }
    int B = xs / (HOPK * TFR);                      // 16
    dim3 grid(TFR / FPB, B);
    causal_stft_kernel<<<grid, NT>>>(x, w, (float*)d_out);
}